// round 1
// baseline (speedup 1.0000x reference)
#include <cuda_runtime.h>
#include <math.h>

#define Hn 300
#define Wn 300
#define Cn 4
#define Mn 4096
#define MT 32          // m-values per block
#define HT 12          // h rows per shared tile (300 % 12 == 0)
#define TPB 256
#define TWO_PI_F 6.2831853071795864769f

// Scratch (allocation-free rule: __device__ globals)
__device__ float2 g_sim[Cn * Hn * Wn];
__device__ float2 g_k[Cn * Mn];

// ---------------------------------------------------------------------------
// Kernel 1: sim[c,h,w] = csm[c,h,w] * img[h,w]   (complex * real)
// ---------------------------------------------------------------------------
__global__ void prep_kernel(const float* __restrict__ img,
                            const float* __restrict__ csm) {
    int idx = blockIdx.x * blockDim.x + threadIdx.x;
    if (idx < Cn * Hn * Wn) {
        int hw = idx % (Hn * Wn);
        float v = img[hw];
        g_sim[idx] = make_float2(csm[2 * idx] * v, csm[2 * idx + 1] * v);
    }
}

// ---------------------------------------------------------------------------
// Kernel 2: k[c,m] = (1/300) * sum_{h,w} sim[c,h,w] * ey[m,h] * ez[m,w]
//
// Block: 32 m-values. Warp w owns m-group of 4, all 4 coils (16 complex accs).
// Lanes split the w dimension; h tiled through shared memory.
// ---------------------------------------------------------------------------
__global__ void __launch_bounds__(TPB, 1) nufft_kernel(const float* __restrict__ omega) {
    extern __shared__ float2 sh[];
    float2* ezs   = sh;                      // [MT][Wn]
    float2* simsh = sh + MT * Wn;            // [Cn][HT][Wn]
    float2* eysh  = simsh + Cn * HT * Wn;    // [MT][HT]

    const int tid  = threadIdx.x;
    const int warp = tid >> 5;
    const int lane = tid & 31;
    const int mBlock = blockIdx.x * MT;
    const int mWarp  = warp * 4;             // warp's first m within the block

    // --- Build ez table: ez[mm][w] = exp(-2*pi*i * omega1[m] * (w - 150)) ---
    for (int idx = tid; idx < MT * Wn; idx += TPB) {
        int mm = idx / Wn;
        int w  = idx - mm * Wn;
        float om = omega[Mn + mBlock + mm];          // omega[1][m]
        float ph = -TWO_PI_F * om * (float)(w - 150);
        float s, c;
        sincosf(ph, &s, &c);
        ezs[idx] = make_float2(c, s);
    }

    // Accumulators: [j = m within warp group][coil]
    float2 acc[4][Cn];
#pragma unroll
    for (int j = 0; j < 4; j++)
#pragma unroll
        for (int c = 0; c < Cn; c++)
            acc[j][c] = make_float2(0.0f, 0.0f);

    // Hoist omega[0][m] for the warp's 4 m-values (for ey computation below)
    for (int h0 = 0; h0 < Hn; h0 += HT) {
        __syncthreads();
        // --- Load sim tile [Cn][HT][Wn] (coalesced) ---
        for (int idx = tid; idx < Cn * HT * Wn; idx += TPB) {
            int c  = idx / (HT * Wn);
            int r  = idx - c * (HT * Wn);
            int hh = r / Wn;
            int w  = r - hh * Wn;
            simsh[idx] = g_sim[(c * Hn + (h0 + hh)) * Wn + w];
        }
        // --- ey tile [MT][HT]: exp(-2*pi*i * omega0[m] * (h - 150)) ---
        for (int idx = tid; idx < MT * HT; idx += TPB) {
            int mm = idx / HT;
            int hh = idx - mm * HT;
            float om = omega[mBlock + mm];           // omega[0][m]
            float ph = -TWO_PI_F * om * (float)(h0 + hh - 150);
            float s, c;
            sincosf(ph, &s, &c);
            eysh[idx] = make_float2(c, s);
        }
        __syncthreads();

        for (int hh = 0; hh < HT; hh++) {
            float2 ph[4];
#pragma unroll
            for (int j = 0; j < 4; j++)
                ph[j] = eysh[(mWarp + j) * HT + hh];

            const float2* simrow0 = simsh + (0 * HT + hh) * Wn;
            const float2* simrow1 = simsh + (1 * HT + hh) * Wn;
            const float2* simrow2 = simsh + (2 * HT + hh) * Wn;
            const float2* simrow3 = simsh + (3 * HT + hh) * Wn;

            for (int w = lane; w < Wn; w += 32) {
                float2 s0 = simrow0[w];
                float2 s1 = simrow1[w];
                float2 s2 = simrow2[w];
                float2 s3 = simrow3[w];
#pragma unroll
                for (int j = 0; j < 4; j++) {
                    float2 e = ezs[(mWarp + j) * Wn + w];
                    // p = ez * ey  (full phase for this (m,h,w))
                    float pr = e.x * ph[j].x - e.y * ph[j].y;
                    float pi = e.x * ph[j].y + e.y * ph[j].x;
                    // acc[j][c] += sim[c] * p
                    acc[j][0].x += s0.x * pr - s0.y * pi;
                    acc[j][0].y += s0.x * pi + s0.y * pr;
                    acc[j][1].x += s1.x * pr - s1.y * pi;
                    acc[j][1].y += s1.x * pi + s1.y * pr;
                    acc[j][2].x += s2.x * pr - s2.y * pi;
                    acc[j][2].y += s2.x * pi + s2.y * pr;
                    acc[j][3].x += s3.x * pr - s3.y * pi;
                    acc[j][3].y += s3.x * pi + s3.y * pr;
                }
            }
        }
    }

    // --- Warp reduction over lanes (lanes held disjoint w slices) ---
#pragma unroll
    for (int off = 16; off; off >>= 1) {
#pragma unroll
        for (int j = 0; j < 4; j++)
#pragma unroll
            for (int c = 0; c < Cn; c++) {
                acc[j][c].x += __shfl_down_sync(0xffffffffu, acc[j][c].x, off);
                acc[j][c].y += __shfl_down_sync(0xffffffffu, acc[j][c].y, off);
            }
    }

    if (lane == 0) {
        const float invs = 1.0f / 300.0f;   // 1/sqrt(H*W)
#pragma unroll
        for (int j = 0; j < 4; j++) {
            int m = mBlock + mWarp + j;
#pragma unroll
            for (int c = 0; c < Cn; c++)
                g_k[c * Mn + m] = make_float2(acc[j][c].x * invs, acc[j][c].y * invs);
        }
    }
}

// ---------------------------------------------------------------------------
// Kernel 3: loss = mean over (2,C,M) of (w(m)*(k - kd)).{re,im}^2
// ---------------------------------------------------------------------------
__global__ void loss_kernel(const float* __restrict__ omega,
                            const float* __restrict__ kdata,
                            float* __restrict__ out) {
    __shared__ float red[TPB];
    float s = 0.0f;
    for (int idx = threadIdx.x; idx < Cn * Mn; idx += TPB) {
        int m = idx % Mn;
        float2 k = g_k[idx];
        float kr = kdata[2 * idx];
        float ki = kdata[2 * idx + 1];
        float o0 = omega[m] * TWO_PI_F;
        float o1 = omega[Mn + m] * TWO_PI_F;
        float wgt = sqrtf(o0 * o0 + o1 * o1) + 1.0f;
        float dr = wgt * (k.x - kr);
        float di = wgt * (k.y - ki);
        s += dr * dr + di * di;
    }
    red[threadIdx.x] = s;
    __syncthreads();
    for (int off = TPB / 2; off; off >>= 1) {
        if (threadIdx.x < off) red[threadIdx.x] += red[threadIdx.x + off];
        __syncthreads();
    }
    if (threadIdx.x == 0)
        out[0] = red[0] / (float)(2 * Cn * Mn);
}

// ---------------------------------------------------------------------------
extern "C" void kernel_launch(void* const* d_in, const int* in_sizes, int n_in,
                              void* d_out, int out_size) {
    const float* img   = (const float*)d_in[0];   // (300,300,1)
    const float* kdata = (const float*)d_in[1];   // (1,4,4096,2)
    const float* omega = (const float*)d_in[2];   // (1,2,4096)
    // d_in[3] = all_dcomp (unused by reference)
    const float* csm   = (const float*)d_in[4];   // (4,300,300,2)
    float* out = (float*)d_out;

    prep_kernel<<<(Cn * Hn * Wn + 255) / 256, 256>>>(img, csm);

    size_t smem = (size_t)(MT * Wn + Cn * HT * Wn + MT * HT) * sizeof(float2);
    cudaFuncSetAttribute(nufft_kernel, cudaFuncAttributeMaxDynamicSharedMemorySize,
                         (int)smem);
    nufft_kernel<<<Mn / MT, TPB, smem>>>(omega);

    loss_kernel<<<1, TPB>>>(omega, kdata, out);
}

// round 3
// speedup vs baseline: 4.7650x; 4.7650x over previous
#include <cuda_runtime.h>
#include <math.h>
#include <stdint.h>

#define Hn 300
#define Wn 300
#define Cn 4
#define Mn 4096
#define TWO_PI_F 6.2831853071795864769f

// GEMM geometry: T[m=4096, ch=1280pad] = sum_k A'[m,k] * B[ch,k], K=608
#define KDIM 608
#define KT_TOT 76          // K tiles of 8
#define MT_TOT 256         // M tiles of 16
#define NT_TOT 160         // N tiles of 8 (1280 cols)
#define CHPAD 1280
#define NCHUNK 19          // 76 kt / 4 per chunk
#define STAGES 3

#define A_STAGE_BYTES 16384    // 4 kt * 8 mt * 32 lanes * 16B
#define B_STAGE_BYTES 32768    // 4 kt * 32 nt * 32 lanes * 8B
#define STAGE_BYTES (A_STAGE_BYTES + B_STAGE_BYTES)
#define SMEM_DYN (STAGES * STAGE_BYTES)

// ---------------------------------------------------------------------------
// Scratch (allocation-free rule: __device__ globals)
// ---------------------------------------------------------------------------
__device__ __align__(128) float g_Ap [KT_TOT * MT_TOT * 128];  // frag-major A
__device__ __align__(128) float g_Bpr[KT_TOT * NT_TOT * 64];   // frag-major B (re)
__device__ __align__(128) float g_Bpi[KT_TOT * NT_TOT * 64];   // frag-major B (im)
__device__ __align__(128) float g_Tr[Mn * CHPAD];
__device__ __align__(128) float g_Ti[Mn * CHPAD];
__device__ float g_part[Cn * Mn];

// ---------------------------------------------------------------------------
// Helpers
// ---------------------------------------------------------------------------
__device__ __forceinline__ uint32_t smem_u32(const void* p) {
    uint32_t a;
    asm("{ .reg .u64 t; cvta.to.shared.u64 t, %1; cvt.u32.u64 %0, t; }" : "=r"(a) : "l"(p));
    return a;
}
__device__ __forceinline__ float to_tf32(float x) {
    uint32_t o;
    asm("cvt.rna.tf32.f32 %0, %1;" : "=r"(o) : "f"(x));
    return __uint_as_float(o);
}
#define CP_ASYNC16(dst, src) asm volatile("cp.async.cg.shared.global [%0], [%1], 16;" :: "r"(dst), "l"(src) : "memory")
#define CP_COMMIT()          asm volatile("cp.async.commit_group;" ::: "memory")
#define CP_WAIT(n)           asm volatile("cp.async.wait_group %0;" :: "n"(n) : "memory")

__device__ __forceinline__ void lds128(uint32_t* r, uint32_t a) {
    asm volatile("ld.shared.v4.b32 {%0,%1,%2,%3}, [%4];"
                 : "=r"(r[0]), "=r"(r[1]), "=r"(r[2]), "=r"(r[3]) : "r"(a));
}
__device__ __forceinline__ void lds64(uint32_t* r, uint32_t a) {
    asm volatile("ld.shared.v2.b32 {%0,%1}, [%2];" : "=r"(r[0]), "=r"(r[1]) : "r"(a));
}
__device__ __forceinline__ void mma_tf32(float* c, const uint32_t* a, const uint32_t* b) {
    asm volatile(
        "mma.sync.aligned.m16n8k8.row.col.f32.tf32.tf32.f32 "
        "{%0,%1,%2,%3}, {%4,%5,%6,%7}, {%8,%9}, {%0,%1,%2,%3};"
        : "+f"(c[0]), "+f"(c[1]), "+f"(c[2]), "+f"(c[3])
        : "r"(a[0]), "r"(a[1]), "r"(a[2]), "r"(a[3]), "r"(b[0]), "r"(b[1]));
}

// ---------------------------------------------------------------------------
// Prep A (fragment-major): A'[m,k] = k<300 ? cos(ph) : k<600 ? sin(ph) : 0
//   ph = -2*pi*omega1[m]*(w-150), w = k mod 300
// Fragment mapping (m16n8k8 A, row-major):
//   a0:(g, t4)  a1:(g+8, t4)  a2:(g, t4+4)  a3:(g+8, t4+4)   g=lane/4, t4=lane%4
// ---------------------------------------------------------------------------
__global__ void prep_Ap(const float* __restrict__ omega) {
    int idx = blockIdx.x * blockDim.x + threadIdx.x;
    if (idx >= KT_TOT * MT_TOT * 128) return;
    int r  = idx & 3;
    int t  = (idx >> 2) & 31;
    int mt = (idx >> 7) & 255;
    int kt = idx >> 15;
    int m = mt * 16 + (t >> 2) + (r & 1) * 8;
    int k = kt * 8 + (t & 3) + (r >> 1) * 4;
    float v = 0.0f;
    if (k < 600) {
        int w = (k < 300) ? k : (k - 300);
        float ph = -TWO_PI_F * omega[Mn + m] * (float)(w - 150);
        float s, c;
        sincosf(ph, &s, &c);
        v = (k < 300) ? c : s;
    }
    g_Ap[idx] = to_tf32(v);
}

// ---------------------------------------------------------------------------
// Prep B (fragment-major, both re and im weight matrices):
//   Br[ch,k] = k<300 ? simr : -simi ;  Bi[ch,k] = k<300 ? simi : simr
//   sim[c,h,w] = csm[c,h,w] * img[h,w], ch = c*300+h, w = k mod 300
// Fragment mapping (B, col-major k x n): b0:(k=t4, n=g), b1:(k=t4+4, n=g)
// ---------------------------------------------------------------------------
__global__ void prep_Bp(const float* __restrict__ img, const float* __restrict__ csm) {
    int idx = blockIdx.x * blockDim.x + threadIdx.x;
    if (idx >= KT_TOT * NT_TOT * 64) return;
    int r  = idx & 1;
    int t  = (idx >> 1) & 31;
    int nt = (idx >> 6) % NT_TOT;
    int kt = idx / (64 * NT_TOT);
    int ch = nt * 8 + (t >> 2);
    int k  = kt * 8 + (t & 3) + r * 4;
    float br = 0.0f, bi = 0.0f;
    if (ch < 1200 && k < 600) {
        int c = ch / 300;
        int h = ch - c * 300;
        int w = (k < 300) ? k : (k - 300);
        int base = (c * 300 + h) * 300 + w;
        float v = img[h * 300 + w];
        float sr = csm[2 * base] * v;
        float si = csm[2 * base + 1] * v;
        if (k < 300) { br = sr;  bi = si; }
        else         { br = -si; bi = sr; }
    }
    g_Bpr[idx] = to_tf32(br);
    g_Bpi[idx] = to_tf32(bi);
}

// ---------------------------------------------------------------------------
// GEMM: CTA 128x256, warp 64x64 (2x4 warp grid), K-chunk 32, 3-stage cp.async
// grid: (32 mTiles, 5 nTiles, 2 re/im)
// ---------------------------------------------------------------------------
__global__ void __launch_bounds__(256, 1) gemm_kernel() {
    extern __shared__ __align__(128) char dsm[];
    const int tid  = threadIdx.x;
    const int wid  = tid >> 5;
    const int lane = tid & 31;
    const int warp_m = wid & 1;          // 0..1 -> 64 rows each
    const int warp_n = wid >> 1;         // 0..3 -> 64 cols each
    const int mTile = blockIdx.x;
    const int nTile = blockIdx.y;
    const float* __restrict__ Bsrc = blockIdx.z ? g_Bpi : g_Bpr;
    float* __restrict__ Tout = blockIdx.z ? g_Ti : g_Tr;

    const uint32_t smem_base = smem_u32(dsm);

    float acc[4][8][4];
#pragma unroll
    for (int i = 0; i < 4; i++)
#pragma unroll
        for (int j = 0; j < 8; j++)
#pragma unroll
            for (int q = 0; q < 4; q++) acc[i][j][q] = 0.0f;

    auto load_chunk = [&](int chunk, int stage) {
        const int kt0 = chunk * 4;
        const uint32_t sA = smem_base + stage * STAGE_BYTES;
        const uint32_t sB = sA + A_STAGE_BYTES;
        // A: 16KB = 1024 x 16B segs; block = (ktl,mtl) 512B, seg-in-block = lane
#pragma unroll
        for (int i = 0; i < 4; i++) {
            int sidx = i * 256 + tid;
            int blk = sidx >> 5, inner = sidx & 31;
            int ktl = blk >> 3, mtl = blk & 7;
            const float* src = g_Ap +
                ((size_t)(kt0 + ktl) * MT_TOT + (mTile * 8 + mtl)) * 128 + inner * 4;
            CP_ASYNC16(sA + sidx * 16, src);
        }
        // B: 32KB = 2048 x 16B segs; block = (ktl,ntl) 256B = 16 segs
#pragma unroll
        for (int i = 0; i < 8; i++) {
            int sidx = i * 256 + tid;
            int blk = sidx >> 4, inner = sidx & 15;
            int ktl = blk >> 5, ntl = blk & 31;
            const float* src = Bsrc +
                ((size_t)(kt0 + ktl) * NT_TOT + (nTile * 32 + ntl)) * 64 + inner * 4;
            CP_ASYNC16(sB + sidx * 16, src);
        }
        CP_COMMIT();
    };

    load_chunk(0, 0);
    load_chunk(1, 1);
    load_chunk(2, 2);

    for (int j = 0; j < NCHUNK; j++) {
        if (j < 17)       { CP_WAIT(2); }
        else if (j == 17) { CP_WAIT(1); }
        else              { CP_WAIT(0); }
        __syncthreads();

        const int stage = j % 3;
        const uint32_t sA = smem_base + stage * STAGE_BYTES;
        const uint32_t sB = sA + A_STAGE_BYTES;
#pragma unroll
        for (int ktl = 0; ktl < 4; ktl++) {
            uint32_t a[4][4], b[8][2];
#pragma unroll
            for (int i = 0; i < 4; i++)
                lds128(a[i], sA + (uint32_t)(((ktl * 8) + warp_m * 4 + i) * 32 + lane) * 16);
#pragma unroll
            for (int jn = 0; jn < 8; jn++)
                lds64(b[jn], sB + (uint32_t)(((ktl * 32) + warp_n * 8 + jn) * 32 + lane) * 8);
#pragma unroll
            for (int i = 0; i < 4; i++)
#pragma unroll
                for (int jn = 0; jn < 8; jn++)
                    mma_tf32(acc[i][jn], a[i], b[jn]);
        }
        __syncthreads();

        if (j + 3 < NCHUNK) load_chunk(j + 3, stage);
    }

    // Epilogue: C frag (m16n8): c0:(g,2t) c1:(g,2t+1) c2:(g+8,2t) c3:(g+8,2t+1)
    const size_t rowBase = (size_t)mTile * 128 + warp_m * 64 + (lane >> 2);
    const int colBase = nTile * 256 + warp_n * 64 + 2 * (lane & 3);
#pragma unroll
    for (int i = 0; i < 4; i++) {
        size_t r0 = rowBase + i * 16;
#pragma unroll
        for (int jn = 0; jn < 8; jn++) {
            int col = colBase + jn * 8;
            *(float2*)&Tout[r0 * CHPAD + col] = make_float2(acc[i][jn][0], acc[i][jn][1]);
            *(float2*)&Tout[(r0 + 8) * CHPAD + col] = make_float2(acc[i][jn][2], acc[i][jn][3]);
        }
    }
}

// ---------------------------------------------------------------------------
// Stage 2: k[c,m] = (1/300)*sum_h (Tr+i Ti)[m, c*300+h] * exp(-2pi i om0 (h-150))
// then per-(c,m) weighted squared error. One warp per (c,m).
// ---------------------------------------------------------------------------
__global__ void __launch_bounds__(256) stage2_kernel(const float* __restrict__ omega,
                                                     const float* __restrict__ kdata) {
    const int wid = threadIdx.x >> 5;
    const int lane = threadIdx.x & 31;
    const int g = blockIdx.x * 8 + wid;
    const int m = g & (Mn - 1);
    const int c = g >> 12;

    const float om0 = omega[m];
    const float* Trr = g_Tr + (size_t)m * CHPAD + c * 300;
    const float* Tii = g_Ti + (size_t)m * CHPAD + c * 300;

    float accr = 0.0f, acci = 0.0f;
    for (int h = lane; h < Hn; h += 32) {
        float ph = -TWO_PI_F * om0 * (float)(h - 150);
        float s, co;
        sincosf(ph, &s, &co);
        float tr = Trr[h];
        float ti = Tii[h];
        accr += tr * co - ti * s;
        acci += tr * s + ti * co;
    }
#pragma unroll
    for (int off = 16; off; off >>= 1) {
        accr += __shfl_down_sync(0xffffffffu, accr, off);
        acci += __shfl_down_sync(0xffffffffu, acci, off);
    }
    if (lane == 0) {
        const float inv = 1.0f / 300.0f;
        float kr = accr * inv, ki = acci * inv;
        float o0 = om0 * TWO_PI_F;
        float o1 = omega[Mn + m] * TWO_PI_F;
        float wgt = sqrtf(o0 * o0 + o1 * o1) + 1.0f;
        float dr = wgt * (kr - kdata[2 * (c * Mn + m)]);
        float di = wgt * (ki - kdata[2 * (c * Mn + m) + 1]);
        g_part[g] = dr * dr + di * di;
    }
}

__global__ void reduce_kernel(float* __restrict__ out) {
    __shared__ float red[256];
    float s = 0.0f;
    for (int i = threadIdx.x; i < Cn * Mn; i += 256) s += g_part[i];
    red[threadIdx.x] = s;
    __syncthreads();
    for (int off = 128; off; off >>= 1) {
        if (threadIdx.x < off) red[threadIdx.x] += red[threadIdx.x + off];
        __syncthreads();
    }
    if (threadIdx.x == 0) out[0] = red[0] / (float)(2 * Cn * Mn);
}

// ---------------------------------------------------------------------------
extern "C" void kernel_launch(void* const* d_in, const int* in_sizes, int n_in,
                              void* d_out, int out_size) {
    const float* img   = (const float*)d_in[0];   // (300,300,1)
    const float* kdata = (const float*)d_in[1];   // (1,4,4096,2)
    const float* omega = (const float*)d_in[2];   // (1,2,4096)
    const float* csm   = (const float*)d_in[4];   // (4,300,300,2)
    float* out = (float*)d_out;

    prep_Ap<<<(KT_TOT * MT_TOT * 128 + 255) / 256, 256>>>(omega);
    prep_Bp<<<(KT_TOT * NT_TOT * 64 + 255) / 256, 256>>>(img, csm);

    cudaFuncSetAttribute(gemm_kernel, cudaFuncAttributeMaxDynamicSharedMemorySize, SMEM_DYN);
    gemm_kernel<<<dim3(Mn / 128, CHPAD / 256, 2), 256, SMEM_DYN>>>();

    stage2_kernel<<<(Cn * Mn) / 8, 256>>>(omega, kdata);
    reduce_kernel<<<1, 256>>>(out);
}

// round 4
// speedup vs baseline: 8.4771x; 1.7790x over previous
#include <cuda_runtime.h>
#include <cuda_fp16.h>
#include <math.h>
#include <stdint.h>

#define Hn 300
#define Wn 300
#define Cn 4
#define Mn 4096
#define TWO_PI_F 6.2831853071795864769f

// GEMM: T[m=4096, ch=1280pad] = sum_k A'[m,k] * B[ch,k], K=608 (fp16 in, f32 acc)
#define KDIM 608
#define KT_TOT 38          // K tiles of 16
#define MT_TOT 256         // M tiles of 16
#define NT_TOT 160         // N tiles of 8
#define CHPAD 1280
#define NCHUNK 19          // 38 kt / 2 per chunk (K-chunk = 32)
#define STAGES 3

#define A_STAGE_BYTES 8192     // 2 kt * 8 mt * 32 lanes * 16B
#define B_STAGE_BYTES 8192     // 2 kt * 16 nt * 32 lanes * 8B
#define STAGE_BYTES (A_STAGE_BYTES + B_STAGE_BYTES)
#define SMEM_DYN (STAGES * STAGE_BYTES)   // 49152

// ---------------------------------------------------------------------------
// Scratch (allocation-free rule: __device__ globals)
// ---------------------------------------------------------------------------
__device__ __align__(128) __half2 g_Ap [KT_TOT * MT_TOT * 128];  // frag-major A (5 MB)
__device__ __align__(128) __half2 g_Bpr[KT_TOT * NT_TOT * 64];   // frag-major B re
__device__ __align__(128) __half2 g_Bpi[KT_TOT * NT_TOT * 64];   // frag-major B im
__device__ __align__(128) float g_Tr[Mn * CHPAD];
__device__ __align__(128) float g_Ti[Mn * CHPAD];
__device__ float g_part[Cn * Mn];

// ---------------------------------------------------------------------------
// Helpers
// ---------------------------------------------------------------------------
__device__ __forceinline__ uint32_t smem_u32(const void* p) {
    uint32_t a;
    asm("{ .reg .u64 t; cvta.to.shared.u64 t, %1; cvt.u32.u64 %0, t; }" : "=r"(a) : "l"(p));
    return a;
}
#define CP_ASYNC16(dst, src) asm volatile("cp.async.cg.shared.global [%0], [%1], 16;" :: "r"(dst), "l"(src) : "memory")
#define CP_COMMIT()          asm volatile("cp.async.commit_group;" ::: "memory")
#define CP_WAIT(n)           asm volatile("cp.async.wait_group %0;" :: "n"(n) : "memory")

__device__ __forceinline__ void lds128(uint32_t* r, uint32_t a) {
    asm volatile("ld.shared.v4.b32 {%0,%1,%2,%3}, [%4];"
                 : "=r"(r[0]), "=r"(r[1]), "=r"(r[2]), "=r"(r[3]) : "r"(a));
}
__device__ __forceinline__ void lds64(uint32_t* r, uint32_t a) {
    asm volatile("ld.shared.v2.b32 {%0,%1}, [%2];" : "=r"(r[0]), "=r"(r[1]) : "r"(a));
}
__device__ __forceinline__ void mma_f16(float* c, const uint32_t* a, const uint32_t* b) {
    asm volatile(
        "mma.sync.aligned.m16n8k16.row.col.f32.f16.f16.f32 "
        "{%0,%1,%2,%3}, {%4,%5,%6,%7}, {%8,%9}, {%0,%1,%2,%3};"
        : "+f"(c[0]), "+f"(c[1]), "+f"(c[2]), "+f"(c[3])
        : "r"(a[0]), "r"(a[1]), "r"(a[2]), "r"(a[3]), "r"(b[0]), "r"(b[1]));
}

// ---------------------------------------------------------------------------
// Prep A (fragment-major, m16n8k16 A-frag): A'[m,k] = k<300 ? cos : k<600 ? sin : 0
//   ph = -2*pi*omega1[m]*(w-150), w = k mod 300
// A frag: reg r (0..3): row = g + (r&1)*8, cols = 2t + (r>>1)*8 + {0,1}
// ---------------------------------------------------------------------------
__global__ void prep_Ap(const float* __restrict__ omega) {
    int p = blockIdx.x * blockDim.x + threadIdx.x;     // half2 index
    if (p >= KT_TOT * MT_TOT * 128) return;
    int r    = p & 3;
    int lane = (p >> 2) & 31;
    int mt   = (p >> 7) & 255;
    int kt   = p >> 15;
    int m  = mt * 16 + (lane >> 2) + (r & 1) * 8;
    int k0 = kt * 16 + 2 * (lane & 3) + (r >> 1) * 8;
    float om = omega[Mn + m];
    float v0 = 0.0f, v1 = 0.0f;
    if (k0 < 600) {   // pairs never straddle the 600 boundary (k0 even)
        int w0 = (k0 < 300) ? k0 : (k0 - 300);
        float s, c;
        sincosf(-TWO_PI_F * om * (float)(w0 - 150), &s, &c);
        v0 = (k0 < 300) ? c : s;
        sincosf(-TWO_PI_F * om * (float)(w0 - 149), &s, &c);
        v1 = (k0 < 300) ? c : s;
    }
    g_Ap[p] = __floats2half2_rn(v0, v1);
}

// ---------------------------------------------------------------------------
// Prep B (fragment-major, m16n8k16 B-frag):
//   Br[ch,k] = k<300 ? simr : -simi ;  Bi[ch,k] = k<300 ? simi : simr
//   sim[c,h,w] = csm * img, ch = c*300+h
// B frag: reg r (0..1): col = g, rows = 2t + r*8 + {0,1}
// ---------------------------------------------------------------------------
__global__ void prep_Bp(const float* __restrict__ img, const float* __restrict__ csm) {
    int p = blockIdx.x * blockDim.x + threadIdx.x;     // half2 index
    if (p >= KT_TOT * NT_TOT * 64) return;
    int r    = p & 1;
    int lane = (p >> 1) & 31;
    int nt   = (p >> 6) % NT_TOT;
    int kt   = p / (64 * NT_TOT);
    int ch = nt * 8 + (lane >> 2);
    int k0 = kt * 16 + 2 * (lane & 3) + r * 8;
    float br0 = 0.f, br1 = 0.f, bi0 = 0.f, bi1 = 0.f;
    if (ch < 1200 && k0 < 600) {
        int c = ch / 300;
        int h = ch - c * 300;
        int w0 = (k0 < 300) ? k0 : (k0 - 300);
        int base = (c * 300 + h) * 300 + w0;
        float v0 = img[h * 300 + w0];
        float v1 = img[h * 300 + w0 + 1];
        float sr0 = csm[2 * base] * v0,     si0 = csm[2 * base + 1] * v0;
        float sr1 = csm[2 * base + 2] * v1, si1 = csm[2 * base + 3] * v1;
        if (k0 < 300) { br0 = sr0;  br1 = sr1;  bi0 = si0; bi1 = si1; }
        else          { br0 = -si0; br1 = -si1; bi0 = sr0; bi1 = sr1; }
    }
    g_Bpr[p] = __floats2half2_rn(br0, br1);
    g_Bpi[p] = __floats2half2_rn(bi0, bi1);
}

// ---------------------------------------------------------------------------
// GEMM: CTA 128x128, warp 64x32 (2x4 warps), K-chunk 32, 3-stage cp.async
// grid: (32 mTiles, 10 nTiles, 2 re/im); 2 CTAs/SM
// ---------------------------------------------------------------------------
__global__ void __launch_bounds__(256, 2) gemm_kernel() {
    extern __shared__ __align__(128) char dsm[];
    const int tid  = threadIdx.x;
    const int wid  = tid >> 5;
    const int lane = tid & 31;
    const int warp_m = wid & 1;          // 0..1 -> 64 rows
    const int warp_n = wid >> 1;         // 0..3 -> 32 cols
    const int mTile = blockIdx.x;
    const int nTile = blockIdx.y;
    const __half2* __restrict__ Bsrc = blockIdx.z ? g_Bpi : g_Bpr;
    float* __restrict__ Tout = blockIdx.z ? g_Ti : g_Tr;

    const uint32_t smem_base = smem_u32(dsm);

    float acc[4][4][4];
#pragma unroll
    for (int i = 0; i < 4; i++)
#pragma unroll
        for (int j = 0; j < 4; j++)
#pragma unroll
            for (int q = 0; q < 4; q++) acc[i][j][q] = 0.0f;

    auto load_chunk = [&](int chunk, int stage) {
        const int kt0 = chunk * 2;
        const uint32_t sA = smem_base + stage * STAGE_BYTES;
        const uint32_t sB = sA + A_STAGE_BYTES;
        // A: 8KB = 512 segs of 16B; seg = (ktl*8 + mtl)*32 + lane_s
#pragma unroll
        for (int i = 0; i < 2; i++) {
            int s = i * 256 + tid;
            int ktl = s >> 8, mtl = (s >> 5) & 7, ls = s & 31;
            const __half2* src = g_Ap +
                ((size_t)((kt0 + ktl) * MT_TOT + mTile * 8 + mtl) * 32 + ls) * 4;
            CP_ASYNC16(sA + s * 16, src);
        }
        // B: 8KB = 512 segs; block (ktl,ntl) = 256B = 16 segs
#pragma unroll
        for (int i = 0; i < 2; i++) {
            int s = i * 256 + tid;
            int ktl = s >> 8, ntl = (s >> 4) & 15, inner = s & 15;
            const __half2* src = Bsrc +
                (size_t)((kt0 + ktl) * NT_TOT + nTile * 16 + ntl) * 64 + inner * 4;
            CP_ASYNC16(sB + s * 16, src);
        }
        CP_COMMIT();
    };

    load_chunk(0, 0);
    load_chunk(1, 1);
    load_chunk(2, 2);

    for (int j = 0; j < NCHUNK; j++) {
        if (j < 17)       { CP_WAIT(2); }
        else if (j == 17) { CP_WAIT(1); }
        else              { CP_WAIT(0); }
        __syncthreads();

        const int stage = j % 3;
        const uint32_t sA = smem_base + stage * STAGE_BYTES;
        const uint32_t sB = sA + A_STAGE_BYTES;
#pragma unroll
        for (int ktl = 0; ktl < 2; ktl++) {
            uint32_t a[4][4], b[4][2];
#pragma unroll
            for (int i = 0; i < 4; i++)
                lds128(a[i], sA + (uint32_t)(((ktl * 8) + warp_m * 4 + i) * 32 + lane) * 16);
#pragma unroll
            for (int jn = 0; jn < 4; jn++)
                lds64(b[jn], sB + (uint32_t)(((ktl * 16) + warp_n * 4 + jn) * 32 + lane) * 8);
#pragma unroll
            for (int i = 0; i < 4; i++)
#pragma unroll
                for (int jn = 0; jn < 4; jn++)
                    mma_f16(acc[i][jn], a[i], b[jn]);
        }
        __syncthreads();

        if (j + 3 < NCHUNK) load_chunk(j + 3, stage);
    }

    // Epilogue: c0:(g,2t) c1:(g,2t+1) c2:(g+8,2t) c3:(g+8,2t+1)
    const size_t rowBase = (size_t)mTile * 128 + warp_m * 64 + (lane >> 2);
    const int colBase = nTile * 128 + warp_n * 32 + 2 * (lane & 3);
#pragma unroll
    for (int i = 0; i < 4; i++) {
        size_t r0 = rowBase + i * 16;
#pragma unroll
        for (int jn = 0; jn < 4; jn++) {
            int col = colBase + jn * 8;
            *(float2*)&Tout[r0 * CHPAD + col] = make_float2(acc[i][jn][0], acc[i][jn][1]);
            *(float2*)&Tout[(r0 + 8) * CHPAD + col] = make_float2(acc[i][jn][2], acc[i][jn][3]);
        }
    }
}

// ---------------------------------------------------------------------------
// Stage 2: k[c,m] = (1/300)*sum_h (Tr+i Ti)[m,c*300+h]*exp(-2pi i om0 (h-150))
// Phase recurrence: 2 sincos per lane, then complex-mul step per 32-h stride.
// ---------------------------------------------------------------------------
__global__ void __launch_bounds__(256) stage2_kernel(const float* __restrict__ omega,
                                                     const float* __restrict__ kdata) {
    const int wid = threadIdx.x >> 5;
    const int lane = threadIdx.x & 31;
    const int g = blockIdx.x * 8 + wid;
    const int m = g & (Mn - 1);
    const int c = g >> 12;

    const float om0 = omega[m];
    const float ang = -TWO_PI_F * om0;
    const float* Trr = g_Tr + (size_t)m * CHPAD + c * 300;
    const float* Tii = g_Ti + (size_t)m * CHPAD + c * 300;

    float er, ei, sr, si;
    sincosf(ang * (float)(lane - 150), &ei, &er);   // e = exp(i*ang*(lane-150))
    sincosf(ang * 32.0f, &si, &sr);                 // step = exp(i*ang*32)

    float accr = 0.0f, acci = 0.0f;
    for (int h = lane; h < Hn; h += 32) {
        float tr = Trr[h];
        float ti = Tii[h];
        accr += tr * er - ti * ei;
        acci += tr * ei + ti * er;
        float nr = er * sr - ei * si;
        ei = er * si + ei * sr;
        er = nr;
    }
#pragma unroll
    for (int off = 16; off; off >>= 1) {
        accr += __shfl_down_sync(0xffffffffu, accr, off);
        acci += __shfl_down_sync(0xffffffffu, acci, off);
    }
    if (lane == 0) {
        const float inv = 1.0f / 300.0f;
        float kr = accr * inv, ki = acci * inv;
        float o0 = om0 * TWO_PI_F;
        float o1 = omega[Mn + m] * TWO_PI_F;
        float wgt = sqrtf(o0 * o0 + o1 * o1) + 1.0f;
        float dr = wgt * (kr - kdata[2 * (c * Mn + m)]);
        float di = wgt * (ki - kdata[2 * (c * Mn + m) + 1]);
        g_part[g] = dr * dr + di * di;
    }
}

__global__ void reduce_kernel(float* __restrict__ out) {
    __shared__ float red[256];
    float s = 0.0f;
    for (int i = threadIdx.x; i < Cn * Mn; i += 256) s += g_part[i];
    red[threadIdx.x] = s;
    __syncthreads();
    for (int off = 128; off; off >>= 1) {
        if (threadIdx.x < off) red[threadIdx.x] += red[threadIdx.x + off];
        __syncthreads();
    }
    if (threadIdx.x == 0) out[0] = red[0] / (float)(2 * Cn * Mn);
}

// ---------------------------------------------------------------------------
extern "C" void kernel_launch(void* const* d_in, const int* in_sizes, int n_in,
                              void* d_out, int out_size) {
    const float* img   = (const float*)d_in[0];   // (300,300,1)
    const float* kdata = (const float*)d_in[1];   // (1,4,4096,2)
    const float* omega = (const float*)d_in[2];   // (1,2,4096)
    const float* csm   = (const float*)d_in[4];   // (4,300,300,2)
    float* out = (float*)d_out;

    prep_Ap<<<(KT_TOT * MT_TOT * 128 + 255) / 256, 256>>>(omega);
    prep_Bp<<<(KT_TOT * NT_TOT * 64 + 255) / 256, 256>>>(img, csm);

    cudaFuncSetAttribute(gemm_kernel, cudaFuncAttributeMaxDynamicSharedMemorySize, SMEM_DYN);
    gemm_kernel<<<dim3(Mn / 128, CHPAD / 128, 2), 256, SMEM_DYN>>>();

    stage2_kernel<<<(Cn * Mn) / 8, 256>>>(omega, kdata);
    reduce_kernel<<<1, 256>>>(out);
}

// round 5
// speedup vs baseline: 8.7898x; 1.0369x over previous
#include <cuda_runtime.h>
#include <cuda_fp16.h>
#include <math.h>
#include <stdint.h>

#define Hn 300
#define Wn 300
#define Cn 4
#define Mn 4096
#define TWO_PI_F 6.2831853071795864769f

// GEMM: T[m=4096, ch=1280pad] = sum_k A'[m,k] * B[ch,k], K=608 (fp16 in, f32 acc)
#define KDIM 608
#define KT_TOT 38          // K tiles of 16
#define MT_TOT 256         // M tiles of 16
#define NT_TOT 160         // N tiles of 8
#define CHPAD 1280
#define NCHUNK 19          // K-chunk = 32
#define STAGES 4

#define A_STAGE_BYTES 8192     // 2 kt * 8 mt * 32 lanes * 16B
#define B_STAGE_BYTES 8192     // 2 kt * 16 nt * 32 lanes * 8B
#define STAGE_BYTES (A_STAGE_BYTES + B_STAGE_BYTES)
#define SMEM_DYN (STAGES * STAGE_BYTES)   // 65536

// ---------------------------------------------------------------------------
// Scratch (allocation-free rule: __device__ globals)
// ---------------------------------------------------------------------------
__device__ __align__(128) __half2 g_Ap [KT_TOT * MT_TOT * 128];  // frag-major A
__device__ __align__(128) __half2 g_Bpr[KT_TOT * NT_TOT * 64];   // frag-major B re
__device__ __align__(128) __half2 g_Bpi[KT_TOT * NT_TOT * 64];   // frag-major B im
__device__ __align__(128) __half g_Tr[Mn * CHPAD];               // fp16 T (10.5 MB)
__device__ __align__(128) __half g_Ti[Mn * CHPAD];
__device__ float g_part[Cn * Mn];

// ---------------------------------------------------------------------------
// Helpers
// ---------------------------------------------------------------------------
__device__ __forceinline__ uint32_t smem_u32(const void* p) {
    uint32_t a;
    asm("{ .reg .u64 t; cvta.to.shared.u64 t, %1; cvt.u32.u64 %0, t; }" : "=r"(a) : "l"(p));
    return a;
}
#define CP_ASYNC16(dst, src) asm volatile("cp.async.cg.shared.global [%0], [%1], 16;" :: "r"(dst), "l"(src) : "memory")
#define CP_COMMIT()          asm volatile("cp.async.commit_group;" ::: "memory")
#define CP_WAIT(n)           asm volatile("cp.async.wait_group %0;" :: "n"(n) : "memory")

__device__ __forceinline__ void lds128(uint32_t* r, uint32_t a) {
    asm volatile("ld.shared.v4.b32 {%0,%1,%2,%3}, [%4];"
                 : "=r"(r[0]), "=r"(r[1]), "=r"(r[2]), "=r"(r[3]) : "r"(a));
}
__device__ __forceinline__ void lds64(uint32_t* r, uint32_t a) {
    asm volatile("ld.shared.v2.b32 {%0,%1}, [%2];" : "=r"(r[0]), "=r"(r[1]) : "r"(a));
}
__device__ __forceinline__ void mma_f16(float* c, const uint32_t* a, const uint32_t* b) {
    asm volatile(
        "mma.sync.aligned.m16n8k16.row.col.f32.f16.f16.f32 "
        "{%0,%1,%2,%3}, {%4,%5,%6,%7}, {%8,%9}, {%0,%1,%2,%3};"
        : "+f"(c[0]), "+f"(c[1]), "+f"(c[2]), "+f"(c[3])
        : "r"(a[0]), "r"(a[1]), "r"(a[2]), "r"(a[3]), "r"(b[0]), "r"(b[1]));
}

// ---------------------------------------------------------------------------
// Prep A (fragment-major, m16n8k16 A-frag): A'[m,k] = k<300 ? cos : k<600 ? sin : 0
//   ph = -2*pi*omega1[m]*(w-150), w = k mod 300
// ---------------------------------------------------------------------------
__global__ void prep_Ap(const float* __restrict__ omega) {
    int p = blockIdx.x * blockDim.x + threadIdx.x;     // half2 index
    if (p >= KT_TOT * MT_TOT * 128) return;
    int r    = p & 3;
    int lane = (p >> 2) & 31;
    int mt   = (p >> 7) & 255;
    int kt   = p >> 15;
    int m  = mt * 16 + (lane >> 2) + (r & 1) * 8;
    int k0 = kt * 16 + 2 * (lane & 3) + (r >> 1) * 8;
    float om = omega[Mn + m];
    float v0 = 0.0f, v1 = 0.0f;
    if (k0 < 600) {
        int w0 = (k0 < 300) ? k0 : (k0 - 300);
        float s, c;
        sincosf(-TWO_PI_F * om * (float)(w0 - 150), &s, &c);
        v0 = (k0 < 300) ? c : s;
        sincosf(-TWO_PI_F * om * (float)(w0 - 149), &s, &c);
        v1 = (k0 < 300) ? c : s;
    }
    g_Ap[p] = __floats2half2_rn(v0, v1);
}

// ---------------------------------------------------------------------------
// Prep B (fragment-major, m16n8k16 B-frag):
//   Br[ch,k] = k<300 ? simr : -simi ;  Bi[ch,k] = k<300 ? simi : simr
// ---------------------------------------------------------------------------
__global__ void prep_Bp(const float* __restrict__ img, const float* __restrict__ csm) {
    int p = blockIdx.x * blockDim.x + threadIdx.x;     // half2 index
    if (p >= KT_TOT * NT_TOT * 64) return;
    int r    = p & 1;
    int lane = (p >> 1) & 31;
    int nt   = (p >> 6) % NT_TOT;
    int kt   = p / (64 * NT_TOT);
    int ch = nt * 8 + (lane >> 2);
    int k0 = kt * 16 + 2 * (lane & 3) + r * 8;
    float br0 = 0.f, br1 = 0.f, bi0 = 0.f, bi1 = 0.f;
    if (ch < 1200 && k0 < 600) {
        int c = ch / 300;
        int h = ch - c * 300;
        int w0 = (k0 < 300) ? k0 : (k0 - 300);
        int base = (c * 300 + h) * 300 + w0;
        float v0 = img[h * 300 + w0];
        float v1 = img[h * 300 + w0 + 1];
        float sr0 = csm[2 * base] * v0,     si0 = csm[2 * base + 1] * v0;
        float sr1 = csm[2 * base + 2] * v1, si1 = csm[2 * base + 3] * v1;
        if (k0 < 300) { br0 = sr0;  br1 = sr1;  bi0 = si0; bi1 = si1; }
        else          { br0 = -si0; br1 = -si1; bi0 = sr0; bi1 = sr1; }
    }
    g_Bpr[p] = __floats2half2_rn(br0, br1);
    g_Bpi[p] = __floats2half2_rn(bi0, bi1);
}

// ---------------------------------------------------------------------------
// GEMM: CTA 128x128, warp 64x32 (2x4 warps), K-chunk 32, 4-stage cp.async,
// single barrier per chunk. grid: (32 mTiles, 10 nTiles, 2 re/im); 2 CTAs/SM.
// ---------------------------------------------------------------------------
__global__ void __launch_bounds__(256, 2) gemm_kernel() {
    extern __shared__ __align__(128) char dsm[];
    const int tid  = threadIdx.x;
    const int wid  = tid >> 5;
    const int lane = tid & 31;
    const int warp_m = wid & 1;
    const int warp_n = wid >> 1;
    const int mTile = blockIdx.x;
    const int nTile = blockIdx.y;
    const __half2* __restrict__ Bsrc = blockIdx.z ? g_Bpi : g_Bpr;
    __half* __restrict__ Tout = blockIdx.z ? g_Ti : g_Tr;

    const uint32_t smem_base = smem_u32(dsm);

    float acc[4][4][4];
#pragma unroll
    for (int i = 0; i < 4; i++)
#pragma unroll
        for (int j = 0; j < 4; j++)
#pragma unroll
            for (int q = 0; q < 4; q++) acc[i][j][q] = 0.0f;

    auto load_chunk = [&](int chunk, int stage) {
        const int kt0 = chunk * 2;
        const uint32_t sA = smem_base + stage * STAGE_BYTES;
        const uint32_t sB = sA + A_STAGE_BYTES;
#pragma unroll
        for (int i = 0; i < 2; i++) {
            int s = i * 256 + tid;
            int ktl = s >> 8, mtl = (s >> 5) & 7, ls = s & 31;
            const __half2* src = g_Ap +
                ((size_t)((kt0 + ktl) * MT_TOT + mTile * 8 + mtl) * 32 + ls) * 4;
            CP_ASYNC16(sA + s * 16, src);
        }
#pragma unroll
        for (int i = 0; i < 2; i++) {
            int s = i * 256 + tid;
            int ktl = s >> 8, ntl = (s >> 4) & 15, inner = s & 15;
            const __half2* src = Bsrc +
                (size_t)((kt0 + ktl) * NT_TOT + nTile * 16 + ntl) * 64 + inner * 4;
            CP_ASYNC16(sB + s * 16, src);
        }
        CP_COMMIT();
    };

    load_chunk(0, 0);
    load_chunk(1, 1);
    load_chunk(2, 2);

    for (int j = 0; j < NCHUNK; j++) {
        if (j < 17)       { CP_WAIT(2); }
        else if (j == 17) { CP_WAIT(1); }
        else              { CP_WAIT(0); }
        __syncthreads();

        const int stage = j & 3;
        const uint32_t sA = smem_base + stage * STAGE_BYTES;
        const uint32_t sB = sA + A_STAGE_BYTES;

        // issue next-chunk loads first (targets stage (j+3)&3, fenced by the sync)
        if (j + 3 < NCHUNK) load_chunk(j + 3, (j + 3) & 3);

#pragma unroll
        for (int ktl = 0; ktl < 2; ktl++) {
            uint32_t a[4][4], b[4][2];
#pragma unroll
            for (int i = 0; i < 4; i++)
                lds128(a[i], sA + (uint32_t)(((ktl * 8) + warp_m * 4 + i) * 32 + lane) * 16);
#pragma unroll
            for (int jn = 0; jn < 4; jn++)
                lds64(b[jn], sB + (uint32_t)(((ktl * 16) + warp_n * 4 + jn) * 32 + lane) * 8);
#pragma unroll
            for (int i = 0; i < 4; i++)
#pragma unroll
                for (int jn = 0; jn < 4; jn++)
                    mma_f16(acc[i][jn], a[i], b[jn]);
        }
    }

    // Epilogue (fp16): c0,c1 adjacent cols -> one half2 store
    const size_t rowBase = (size_t)mTile * 128 + warp_m * 64 + (lane >> 2);
    const int colBase = nTile * 128 + warp_n * 32 + 2 * (lane & 3);
#pragma unroll
    for (int i = 0; i < 4; i++) {
        size_t r0 = rowBase + i * 16;
#pragma unroll
        for (int jn = 0; jn < 4; jn++) {
            int col = colBase + jn * 8;
            *(__half2*)&Tout[r0 * CHPAD + col] = __floats2half2_rn(acc[i][jn][0], acc[i][jn][1]);
            *(__half2*)&Tout[(r0 + 8) * CHPAD + col] = __floats2half2_rn(acc[i][jn][2], acc[i][jn][3]);
        }
    }
}

// ---------------------------------------------------------------------------
// Stage 2: k[c,m] = (1/300)*sum_h (Tr+i Ti)[m,c*300+h]*exp(-2pi i om0 (h-150))
// half2 loads (2 h per lane-iter), paired-phasor fold, recurrence step 64.
// ---------------------------------------------------------------------------
__global__ void __launch_bounds__(256) stage2_kernel(const float* __restrict__ omega,
                                                     const float* __restrict__ kdata) {
    const int wid = threadIdx.x >> 5;
    const int lane = threadIdx.x & 31;
    const int g = blockIdx.x * 8 + wid;
    const int m = g & (Mn - 1);
    const int c = g >> 12;

    const float om0 = omega[m];
    const float ang = -TWO_PI_F * om0;
    const __half2* Tr2 = (const __half2*)(g_Tr + (size_t)m * CHPAD + c * 300);
    const __half2* Ti2 = (const __half2*)(g_Ti + (size_t)m * CHPAD + c * 300);

    float er, ei, e1r, e1i, sr, si;
    sincosf(ang * (float)(2 * lane - 150), &ei, &er);  // e = exp(i*ang*(h0-150))
    sincosf(ang, &e1i, &e1r);                          // e1 = exp(i*ang)
    sincosf(ang * 64.0f, &si, &sr);                    // step = exp(i*ang*64)

    float accr = 0.0f, acci = 0.0f;
    for (int idx = lane; idx < 150; idx += 32) {
        float2 tr = __half22float2(Tr2[idx]);
        float2 ti = __half22float2(Ti2[idx]);
        // fold pair: q = T0 + T1 * e1   (complex)
        float qr = tr.x + tr.y * e1r - ti.y * e1i;
        float qi = ti.x + tr.y * e1i + ti.y * e1r;
        // acc += e * q
        accr += er * qr - ei * qi;
        acci += er * qi + ei * qr;
        // e *= step
        float nr = er * sr - ei * si;
        ei = er * si + ei * sr;
        er = nr;
    }
#pragma unroll
    for (int off = 16; off; off >>= 1) {
        accr += __shfl_down_sync(0xffffffffu, accr, off);
        acci += __shfl_down_sync(0xffffffffu, acci, off);
    }
    if (lane == 0) {
        const float inv = 1.0f / 300.0f;
        float kr = accr * inv, ki = acci * inv;
        float o0 = om0 * TWO_PI_F;
        float o1 = omega[Mn + m] * TWO_PI_F;
        float wgt = sqrtf(o0 * o0 + o1 * o1) + 1.0f;
        float dr = wgt * (kr - kdata[2 * (c * Mn + m)]);
        float di = wgt * (ki - kdata[2 * (c * Mn + m) + 1]);
        g_part[g] = dr * dr + di * di;
    }
}

__global__ void reduce_kernel(float* __restrict__ out) {
    __shared__ float red[256];
    float s = 0.0f;
    for (int i = threadIdx.x; i < Cn * Mn; i += 256) s += g_part[i];
    red[threadIdx.x] = s;
    __syncthreads();
    for (int off = 128; off; off >>= 1) {
        if (threadIdx.x < off) red[threadIdx.x] += red[threadIdx.x + off];
        __syncthreads();
    }
    if (threadIdx.x == 0) out[0] = red[0] / (float)(2 * Cn * Mn);
}

// ---------------------------------------------------------------------------
extern "C" void kernel_launch(void* const* d_in, const int* in_sizes, int n_in,
                              void* d_out, int out_size) {
    const float* img   = (const float*)d_in[0];   // (300,300,1)
    const float* kdata = (const float*)d_in[1];   // (1,4,4096,2)
    const float* omega = (const float*)d_in[2];   // (1,2,4096)
    const float* csm   = (const float*)d_in[4];   // (4,300,300,2)
    float* out = (float*)d_out;

    prep_Ap<<<(KT_TOT * MT_TOT * 128 + 255) / 256, 256>>>(omega);
    prep_Bp<<<(KT_TOT * NT_TOT * 64 + 255) / 256, 256>>>(img, csm);

    cudaFuncSetAttribute(gemm_kernel, cudaFuncAttributeMaxDynamicSharedMemorySize, SMEM_DYN);
    gemm_kernel<<<dim3(Mn / 128, CHPAD / 128, 2), 256, SMEM_DYN>>>();

    stage2_kernel<<<(Cn * Mn) / 8, 256>>>(omega, kdata);
    reduce_kernel<<<1, 256>>>(out);
}

// round 6
// speedup vs baseline: 10.7333x; 1.2211x over previous
#include <cuda_runtime.h>
#include <cuda_fp16.h>
#include <math.h>
#include <stdint.h>

#define Hn 300
#define Wn 300
#define Cn 4
#define Mn 4096
#define TWO_PI_F 6.2831853071795864769f

// 3M GEMMs: P_z[m,ch] = sum_k A_z[m,k] * B_z[ch,k],  K = 320 (300 + pad), fp16
//   z=0: cos * Sr ; z=1: sin * Si ; z=2: (cos+sin) * (Sr+Si)
//   Tr = P0 - P1 ; Ti = P2 - P0 - P1
#define KT_TOT 20          // K tiles of 16 -> K=320
#define MT_TOT 256         // M tiles of 16
#define NT_TOT 160         // N tiles of 8
#define CHPAD 1280
#define NCHUNK 10          // K-chunk = 32
#define STAGES 4

#define AP_V (KT_TOT * MT_TOT * 128)   // half2 per A variant
#define BP_V (KT_TOT * NT_TOT * 64)    // half2 per B variant
#define PS   ((size_t)Mn * CHPAD)      // halves per P variant

#define A_STAGE_BYTES 8192
#define B_STAGE_BYTES 8192
#define STAGE_BYTES (A_STAGE_BYTES + B_STAGE_BYTES)
#define SMEM_DYN (STAGES * STAGE_BYTES)   // 65536

// ---------------------------------------------------------------------------
// Scratch (allocation-free rule: __device__ globals)
// ---------------------------------------------------------------------------
__device__ __align__(128) __half2 g_Ap[3 * AP_V];   // frag-major A, 3 variants
__device__ __align__(128) __half2 g_Bp[3 * BP_V];   // frag-major B, 3 variants
__device__ __align__(128) __half  g_P [3 * Mn * CHPAD];  // P0,P1,P2 (31.5 MB)
__device__ float g_part[Cn * Mn];

// ---------------------------------------------------------------------------
// Helpers
// ---------------------------------------------------------------------------
__device__ __forceinline__ uint32_t smem_u32(const void* p) {
    uint32_t a;
    asm("{ .reg .u64 t; cvta.to.shared.u64 t, %1; cvt.u32.u64 %0, t; }" : "=r"(a) : "l"(p));
    return a;
}
#define CP_ASYNC16(dst, src) asm volatile("cp.async.cg.shared.global [%0], [%1], 16;" :: "r"(dst), "l"(src) : "memory")
#define CP_COMMIT()          asm volatile("cp.async.commit_group;" ::: "memory")
#define CP_WAIT(n)           asm volatile("cp.async.wait_group %0;" :: "n"(n) : "memory")

__device__ __forceinline__ void lds128(uint32_t* r, uint32_t a) {
    asm volatile("ld.shared.v4.b32 {%0,%1,%2,%3}, [%4];"
                 : "=r"(r[0]), "=r"(r[1]), "=r"(r[2]), "=r"(r[3]) : "r"(a));
}
__device__ __forceinline__ void lds64(uint32_t* r, uint32_t a) {
    asm volatile("ld.shared.v2.b32 {%0,%1}, [%2];" : "=r"(r[0]), "=r"(r[1]) : "r"(a));
}
__device__ __forceinline__ void mma_f16(float* c, const uint32_t* a, const uint32_t* b) {
    asm volatile(
        "mma.sync.aligned.m16n8k16.row.col.f32.f16.f16.f32 "
        "{%0,%1,%2,%3}, {%4,%5,%6,%7}, {%8,%9}, {%0,%1,%2,%3};"
        : "+f"(c[0]), "+f"(c[1]), "+f"(c[2]), "+f"(c[3])
        : "r"(a[0]), "r"(a[1]), "r"(a[2]), "r"(a[3]), "r"(b[0]), "r"(b[1]));
}

// ---------------------------------------------------------------------------
// Prep A (fragment-major, m16n8k16 A-frag): one thread = one half2 slot,
// writes all 3 variants. A value at (m,k): k<300 ? f(ph) : 0,
// ph = -2*pi*omega1[m]*(k-150).  v0=cos, v1=sin, v2=cos+sin.
// ---------------------------------------------------------------------------
__global__ void prep_Ap(const float* __restrict__ omega) {
    int p = blockIdx.x * blockDim.x + threadIdx.x;
    if (p >= AP_V) return;
    int r    = p & 3;
    int lane = (p >> 2) & 31;
    int mt   = (p >> 7) & 255;
    int kt   = p >> 15;
    int m  = mt * 16 + (lane >> 2) + (r & 1) * 8;
    int k0 = kt * 16 + 2 * (lane & 3) + (r >> 1) * 8;
    float c0 = 0.f, s0 = 0.f, c1 = 0.f, s1 = 0.f;
    if (k0 < 300) {   // pairs never straddle (k0 even, 300 even)
        float om = omega[Mn + m];
        sincosf(-TWO_PI_F * om * (float)(k0 - 150), &s0, &c0);
        sincosf(-TWO_PI_F * om * (float)(k0 - 149), &s1, &c1);
    }
    g_Ap[p]            = __floats2half2_rn(c0, c1);
    g_Ap[AP_V + p]     = __floats2half2_rn(s0, s1);
    g_Ap[2 * AP_V + p] = __floats2half2_rn(c0 + s0, c1 + s1);
}

// ---------------------------------------------------------------------------
// Prep B: one thread = one half2 slot, 3 variants.
// B value at (ch,k): sim = csm*img ; v0=Sr, v1=Si, v2=Sr+Si ; 0 if padded.
// ---------------------------------------------------------------------------
__global__ void prep_Bp(const float* __restrict__ img, const float* __restrict__ csm) {
    int p = blockIdx.x * blockDim.x + threadIdx.x;
    if (p >= BP_V) return;
    int r    = p & 1;
    int lane = (p >> 1) & 31;
    int nt   = (p >> 6) % NT_TOT;
    int kt   = p / (64 * NT_TOT);
    int ch = nt * 8 + (lane >> 2);
    int k0 = kt * 16 + 2 * (lane & 3) + r * 8;
    float sr0 = 0.f, si0 = 0.f, sr1 = 0.f, si1 = 0.f;
    if (ch < 1200 && k0 < 300) {
        int c = ch / 300;
        int h = ch - c * 300;
        int base = (c * 300 + h) * 300 + k0;
        float v0 = img[h * 300 + k0];
        float v1 = img[h * 300 + k0 + 1];
        sr0 = csm[2 * base] * v0;     si0 = csm[2 * base + 1] * v0;
        sr1 = csm[2 * base + 2] * v1; si1 = csm[2 * base + 3] * v1;
    }
    g_Bp[p]            = __floats2half2_rn(sr0, sr1);
    g_Bp[BP_V + p]     = __floats2half2_rn(si0, si1);
    g_Bp[2 * BP_V + p] = __floats2half2_rn(sr0 + si0, sr1 + si1);
}

// ---------------------------------------------------------------------------
// GEMM: CTA 128x128, warp 64x32 (2x4 warps), K-chunk 32, 4-stage cp.async.
// grid: (32 mTiles, 10 nTiles, 3 variants); 2 CTAs/SM.
// ---------------------------------------------------------------------------
__global__ void __launch_bounds__(256, 2) gemm_kernel() {
    extern __shared__ __align__(128) char dsm[];
    const int tid  = threadIdx.x;
    const int wid  = tid >> 5;
    const int lane = tid & 31;
    const int warp_m = wid & 1;
    const int warp_n = wid >> 1;
    const int mTile = blockIdx.x;
    const int nTile = blockIdx.y;
    const __half2* __restrict__ Asrc = g_Ap + (size_t)blockIdx.z * AP_V;
    const __half2* __restrict__ Bsrc = g_Bp + (size_t)blockIdx.z * BP_V;
    __half* __restrict__ Pout = g_P + (size_t)blockIdx.z * PS;

    const uint32_t smem_base = smem_u32(dsm);

    float acc[4][4][4];
#pragma unroll
    for (int i = 0; i < 4; i++)
#pragma unroll
        for (int j = 0; j < 4; j++)
#pragma unroll
            for (int q = 0; q < 4; q++) acc[i][j][q] = 0.0f;

    auto load_chunk = [&](int chunk, int stage) {
        const int kt0 = chunk * 2;
        const uint32_t sA = smem_base + stage * STAGE_BYTES;
        const uint32_t sB = sA + A_STAGE_BYTES;
#pragma unroll
        for (int i = 0; i < 2; i++) {
            int s = i * 256 + tid;
            int ktl = s >> 8, mtl = (s >> 5) & 7, ls = s & 31;
            const __half2* src = Asrc +
                ((size_t)((kt0 + ktl) * MT_TOT + mTile * 8 + mtl) * 32 + ls) * 4;
            CP_ASYNC16(sA + s * 16, src);
        }
#pragma unroll
        for (int i = 0; i < 2; i++) {
            int s = i * 256 + tid;
            int ktl = s >> 8, ntl = (s >> 4) & 15, inner = s & 15;
            const __half2* src = Bsrc +
                (size_t)((kt0 + ktl) * NT_TOT + nTile * 16 + ntl) * 64 + inner * 4;
            CP_ASYNC16(sB + s * 16, src);
        }
        CP_COMMIT();
    };

    load_chunk(0, 0);
    load_chunk(1, 1);
    load_chunk(2, 2);

    for (int j = 0; j < NCHUNK; j++) {
        if (j < 8)       { CP_WAIT(2); }
        else if (j == 8) { CP_WAIT(1); }
        else             { CP_WAIT(0); }
        __syncthreads();

        const int stage = j & 3;
        const uint32_t sA = smem_base + stage * STAGE_BYTES;
        const uint32_t sB = sA + A_STAGE_BYTES;

        if (j + 3 < NCHUNK) load_chunk(j + 3, (j + 3) & 3);

#pragma unroll
        for (int ktl = 0; ktl < 2; ktl++) {
            uint32_t a[4][4], b[4][2];
#pragma unroll
            for (int i = 0; i < 4; i++)
                lds128(a[i], sA + (uint32_t)(((ktl * 8) + warp_m * 4 + i) * 32 + lane) * 16);
#pragma unroll
            for (int jn = 0; jn < 4; jn++)
                lds64(b[jn], sB + (uint32_t)(((ktl * 16) + warp_n * 4 + jn) * 32 + lane) * 8);
#pragma unroll
            for (int i = 0; i < 4; i++)
#pragma unroll
                for (int jn = 0; jn < 4; jn++)
                    mma_f16(acc[i][jn], a[i], b[jn]);
        }
    }

    // Epilogue (fp16)
    const size_t rowBase = (size_t)mTile * 128 + warp_m * 64 + (lane >> 2);
    const int colBase = nTile * 128 + warp_n * 32 + 2 * (lane & 3);
#pragma unroll
    for (int i = 0; i < 4; i++) {
        size_t r0 = rowBase + i * 16;
#pragma unroll
        for (int jn = 0; jn < 4; jn++) {
            int col = colBase + jn * 8;
            *(__half2*)&Pout[r0 * CHPAD + col] = __floats2half2_rn(acc[i][jn][0], acc[i][jn][1]);
            *(__half2*)&Pout[(r0 + 8) * CHPAD + col] = __floats2half2_rn(acc[i][jn][2], acc[i][jn][3]);
        }
    }
}

// ---------------------------------------------------------------------------
// Stage 2: Tr = P0-P1, Ti = P2-P0-P1 on the fly;
// k[c,m] = (1/300)*sum_h (Tr+i Ti) * exp(i*ang*(h-150)), ang = -2*pi*om0.
// uint2 loads: 4 h per lane-iter, 4-term phasor fold, step recurrence 128.
// ---------------------------------------------------------------------------
__global__ void __launch_bounds__(256) stage2_kernel(const float* __restrict__ omega,
                                                     const float* __restrict__ kdata) {
    const int wid = threadIdx.x >> 5;
    const int lane = threadIdx.x & 31;
    const int g = blockIdx.x * 8 + wid;
    const int m = g & (Mn - 1);
    const int c = g >> 12;

    const float om0 = omega[m];
    const float ang = -TWO_PI_F * om0;
    const size_t rowoff = (size_t)m * CHPAD + c * 300;
    const uint2* p0 = (const uint2*)(g_P + rowoff);
    const uint2* p1 = (const uint2*)(g_P + PS + rowoff);
    const uint2* p2 = (const uint2*)(g_P + 2 * PS + rowoff);

    float er, ei, c1, s1, str, sti;
    sincosf(ang * (float)(4 * lane - 150), &ei, &er);  // e = exp(i*ang*(h0-150))
    sincosf(ang, &s1, &c1);                            // e1
    sincosf(ang * 128.0f, &sti, &str);                 // step per iter (32 lanes * 4 h)
    const float e2r = c1 * c1 - s1 * s1, e2i = 2.0f * c1 * s1;
    const float e3r = e2r * c1 - e2i * s1, e3i = e2r * s1 + e2i * c1;

    float accr = 0.0f, acci = 0.0f;
    for (int idx = lane; idx < 75; idx += 32) {
        uint2 a0 = p0[idx], a1 = p1[idx], a2 = p2[idx];
        float2 q0a = __half22float2(*(__half2*)&a0.x);
        float2 q0b = __half22float2(*(__half2*)&a0.y);
        float2 q1a = __half22float2(*(__half2*)&a1.x);
        float2 q1b = __half22float2(*(__half2*)&a1.y);
        float2 q2a = __half22float2(*(__half2*)&a2.x);
        float2 q2b = __half22float2(*(__half2*)&a2.y);

        float tr0 = q0a.x - q1a.x, ti0 = q2a.x - q0a.x - q1a.x;
        float tr1 = q0a.y - q1a.y, ti1 = q2a.y - q0a.y - q1a.y;
        float tr2 = q0b.x - q1b.x, ti2 = q2b.x - q0b.x - q1b.x;
        float tr3 = q0b.y - q1b.y, ti3 = q2b.y - q0b.y - q1b.y;

        // q = T0 + T1*e1 + T2*e2 + T3*e3
        float qr = tr0 + tr1 * c1 - ti1 * s1 + tr2 * e2r - ti2 * e2i + tr3 * e3r - ti3 * e3i;
        float qi = ti0 + tr1 * s1 + ti1 * c1 + tr2 * e2i + ti2 * e2r + tr3 * e3i + ti3 * e3r;

        accr += er * qr - ei * qi;
        acci += er * qi + ei * qr;

        float nr = er * str - ei * sti;
        ei = er * sti + ei * str;
        er = nr;
    }
#pragma unroll
    for (int off = 16; off; off >>= 1) {
        accr += __shfl_down_sync(0xffffffffu, accr, off);
        acci += __shfl_down_sync(0xffffffffu, acci, off);
    }
    if (lane == 0) {
        const float inv = 1.0f / 300.0f;
        float kr = accr * inv, ki = acci * inv;
        float o0 = om0 * TWO_PI_F;
        float o1 = omega[Mn + m] * TWO_PI_F;
        float wgt = sqrtf(o0 * o0 + o1 * o1) + 1.0f;
        float dr = wgt * (kr - kdata[2 * (c * Mn + m)]);
        float di = wgt * (ki - kdata[2 * (c * Mn + m) + 1]);
        g_part[g] = dr * dr + di * di;
    }
}

__global__ void reduce_kernel(float* __restrict__ out) {
    __shared__ float red[256];
    float s = 0.0f;
    for (int i = threadIdx.x; i < Cn * Mn; i += 256) s += g_part[i];
    red[threadIdx.x] = s;
    __syncthreads();
    for (int off = 128; off; off >>= 1) {
        if (threadIdx.x < off) red[threadIdx.x] += red[threadIdx.x + off];
        __syncthreads();
    }
    if (threadIdx.x == 0) out[0] = red[0] / (float)(2 * Cn * Mn);
}

// ---------------------------------------------------------------------------
extern "C" void kernel_launch(void* const* d_in, const int* in_sizes, int n_in,
                              void* d_out, int out_size) {
    const float* img   = (const float*)d_in[0];   // (300,300,1)
    const float* kdata = (const float*)d_in[1];   // (1,4,4096,2)
    const float* omega = (const float*)d_in[2];   // (1,2,4096)
    const float* csm   = (const float*)d_in[4];   // (4,300,300,2)
    float* out = (float*)d_out;

    prep_Ap<<<(AP_V + 255) / 256, 256>>>(omega);
    prep_Bp<<<(BP_V + 255) / 256, 256>>>(img, csm);

    cudaFuncSetAttribute(gemm_kernel, cudaFuncAttributeMaxDynamicSharedMemorySize, SMEM_DYN);
    gemm_kernel<<<dim3(Mn / 128, CHPAD / 128, 3), 256, SMEM_DYN>>>();

    stage2_kernel<<<(Cn * Mn) / 8, 256>>>(omega, kdata);
    reduce_kernel<<<1, 256>>>(out);
}

// round 7
// speedup vs baseline: 11.6145x; 1.0821x over previous
#include <cuda_runtime.h>
#include <cuda_fp16.h>
#include <math.h>
#include <stdint.h>

#define Hn 300
#define Wn 300
#define Cn 4
#define Mn 4096
#define TWO_PI_F 6.2831853071795864769f

// 3M GEMMs: P_z[m,ch] = sum_k A_z[m,k] * B_z[ch,k],  K = 320 (300 + pad), fp16
//   z=0: cos * Sr ; z=1: sin * Si ; z=2: (cos+sin) * (Sr+Si)
//   Tr = P0 - P1 ; Ti = P2 - P0 - P1
#define KT_TOT 20          // K tiles of 16 -> K=320
#define MT_TOT 256         // M tiles of 16
#define NT_TOT 160         // N tiles of 8
#define CHPAD 1280
#define NCHUNK 10          // K-chunk = 32
#define STAGES 4

#define AP_V (KT_TOT * MT_TOT * 128)   // half2 per A variant
#define BP_V (KT_TOT * NT_TOT * 64)    // half2 per B variant
#define PS   ((size_t)Mn * CHPAD)      // halves per P variant

#define A_STAGE_BYTES 8192
#define B_STAGE_BYTES 8192
#define STAGE_BYTES (A_STAGE_BYTES + B_STAGE_BYTES)
#define SMEM_DYN (STAGES * STAGE_BYTES)   // 65536

// ---------------------------------------------------------------------------
// Scratch (allocation-free rule: __device__ globals)
// ---------------------------------------------------------------------------
__device__ __align__(128) __half2 g_Ap[3 * AP_V];   // frag-major A, 3 variants
__device__ __align__(128) __half2 g_Bp[3 * BP_V];   // frag-major B, 3 variants
__device__ __align__(128) __half  g_P [3 * Mn * CHPAD];  // P0,P1,P2 (31.5 MB)
__device__ float g_part[512];

// ---------------------------------------------------------------------------
// Helpers
// ---------------------------------------------------------------------------
__device__ __forceinline__ uint32_t smem_u32(const void* p) {
    uint32_t a;
    asm("{ .reg .u64 t; cvta.to.shared.u64 t, %1; cvt.u32.u64 %0, t; }" : "=r"(a) : "l"(p));
    return a;
}
#define CP_ASYNC16(dst, src) asm volatile("cp.async.cg.shared.global [%0], [%1], 16;" :: "r"(dst), "l"(src) : "memory")
#define CP_COMMIT()          asm volatile("cp.async.commit_group;" ::: "memory")
#define CP_WAIT(n)           asm volatile("cp.async.wait_group %0;" :: "n"(n) : "memory")

__device__ __forceinline__ void lds128(uint32_t* r, uint32_t a) {
    asm volatile("ld.shared.v4.b32 {%0,%1,%2,%3}, [%4];"
                 : "=r"(r[0]), "=r"(r[1]), "=r"(r[2]), "=r"(r[3]) : "r"(a));
}
__device__ __forceinline__ void lds64(uint32_t* r, uint32_t a) {
    asm volatile("ld.shared.v2.b32 {%0,%1}, [%2];" : "=r"(r[0]), "=r"(r[1]) : "r"(a));
}
__device__ __forceinline__ void mma_f16(float* c, const uint32_t* a, const uint32_t* b) {
    asm volatile(
        "mma.sync.aligned.m16n8k16.row.col.f32.f16.f16.f32 "
        "{%0,%1,%2,%3}, {%4,%5,%6,%7}, {%8,%9}, {%0,%1,%2,%3};"
        : "+f"(c[0]), "+f"(c[1]), "+f"(c[2]), "+f"(c[3])
        : "r"(a[0]), "r"(a[1]), "r"(a[2]), "r"(a[3]), "r"(b[0]), "r"(b[1]));
}

// exp(-2*pi*i * f_cycles): reduce in cycles domain, MUFU fast path.
// returns (cos, sin) of the NEGATIVE angle (matches sincosf(-2pi f) convention)
__device__ __forceinline__ float2 phasor(float f) {
    f -= rintf(f);
    float s, c;
    __sincosf(-TWO_PI_F * f, &s, &c);
    return make_float2(c, s);
}
__device__ __forceinline__ float2 cmul(float2 a, float2 b) {
    return make_float2(a.x * b.x - a.y * b.y, a.x * b.y + a.y * b.x);
}

// ---------------------------------------------------------------------------
// Prep A (fragment-major, m16n8k16 A-frag): one thread = one half2 slot,
// writes all 3 variants. v0=cos, v1=sin, v2=cos+sin of -2pi*om1[m]*(k-150).
// ---------------------------------------------------------------------------
__global__ void prep_Ap(const float* __restrict__ omega) {
    int p = blockIdx.x * blockDim.x + threadIdx.x;
    if (p >= AP_V) return;
    int r    = p & 3;
    int lane = (p >> 2) & 31;
    int mt   = (p >> 7) & 255;
    int kt   = p >> 15;
    int m  = mt * 16 + (lane >> 2) + (r & 1) * 8;
    int k0 = kt * 16 + 2 * (lane & 3) + (r >> 1) * 8;
    float c0 = 0.f, s0 = 0.f, c1 = 0.f, s1 = 0.f;
    if (k0 < 300) {   // pairs never straddle (k0 even, 300 even)
        float om = omega[Mn + m];
        float2 e0 = phasor(om * (float)(k0 - 150));
        float2 e1 = phasor(om * (float)(k0 - 149));
        c0 = e0.x; s0 = e0.y; c1 = e1.x; s1 = e1.y;
    }
    g_Ap[p]            = __floats2half2_rn(c0, c1);
    g_Ap[AP_V + p]     = __floats2half2_rn(s0, s1);
    g_Ap[2 * AP_V + p] = __floats2half2_rn(c0 + s0, c1 + s1);
}

// ---------------------------------------------------------------------------
// Prep B: one thread = one half2 slot, 3 variants (Sr, Si, Sr+Si).
// ---------------------------------------------------------------------------
__global__ void prep_Bp(const float* __restrict__ img, const float* __restrict__ csm) {
    int p = blockIdx.x * blockDim.x + threadIdx.x;
    if (p >= BP_V) return;
    int r    = p & 1;
    int lane = (p >> 1) & 31;
    int nt   = (p >> 6) % NT_TOT;
    int kt   = p / (64 * NT_TOT);
    int ch = nt * 8 + (lane >> 2);
    int k0 = kt * 16 + 2 * (lane & 3) + r * 8;
    float sr0 = 0.f, si0 = 0.f, sr1 = 0.f, si1 = 0.f;
    if (ch < 1200 && k0 < 300) {
        int c = ch / 300;
        int h = ch - c * 300;
        int base = (c * 300 + h) * 300 + k0;
        float v0 = img[h * 300 + k0];
        float v1 = img[h * 300 + k0 + 1];
        sr0 = csm[2 * base] * v0;     si0 = csm[2 * base + 1] * v0;
        sr1 = csm[2 * base + 2] * v1; si1 = csm[2 * base + 3] * v1;
    }
    g_Bp[p]            = __floats2half2_rn(sr0, sr1);
    g_Bp[BP_V + p]     = __floats2half2_rn(si0, si1);
    g_Bp[2 * BP_V + p] = __floats2half2_rn(sr0 + si0, sr1 + si1);
}

// ---------------------------------------------------------------------------
// GEMM: CTA 128x128, warp 64x32 (2x4 warps), K-chunk 32, 4-stage cp.async.
// grid: (32 mTiles, 10 nTiles, 3 variants); 2 CTAs/SM.
// ---------------------------------------------------------------------------
__global__ void __launch_bounds__(256, 2) gemm_kernel() {
    extern __shared__ __align__(128) char dsm[];
    const int tid  = threadIdx.x;
    const int wid  = tid >> 5;
    const int lane = tid & 31;
    const int warp_m = wid & 1;
    const int warp_n = wid >> 1;
    const int mTile = blockIdx.x;
    const int nTile = blockIdx.y;
    const __half2* __restrict__ Asrc = g_Ap + (size_t)blockIdx.z * AP_V;
    const __half2* __restrict__ Bsrc = g_Bp + (size_t)blockIdx.z * BP_V;
    __half* __restrict__ Pout = g_P + (size_t)blockIdx.z * PS;

    const uint32_t smem_base = smem_u32(dsm);

    float acc[4][4][4];
#pragma unroll
    for (int i = 0; i < 4; i++)
#pragma unroll
        for (int j = 0; j < 4; j++)
#pragma unroll
            for (int q = 0; q < 4; q++) acc[i][j][q] = 0.0f;

    auto load_chunk = [&](int chunk, int stage) {
        const int kt0 = chunk * 2;
        const uint32_t sA = smem_base + stage * STAGE_BYTES;
        const uint32_t sB = sA + A_STAGE_BYTES;
#pragma unroll
        for (int i = 0; i < 2; i++) {
            int s = i * 256 + tid;
            int ktl = s >> 8, mtl = (s >> 5) & 7, ls = s & 31;
            const __half2* src = Asrc +
                ((size_t)((kt0 + ktl) * MT_TOT + mTile * 8 + mtl) * 32 + ls) * 4;
            CP_ASYNC16(sA + s * 16, src);
        }
#pragma unroll
        for (int i = 0; i < 2; i++) {
            int s = i * 256 + tid;
            int ktl = s >> 8, ntl = (s >> 4) & 15, inner = s & 15;
            const __half2* src = Bsrc +
                (size_t)((kt0 + ktl) * NT_TOT + nTile * 16 + ntl) * 64 + inner * 4;
            CP_ASYNC16(sB + s * 16, src);
        }
        CP_COMMIT();
    };

    load_chunk(0, 0);
    load_chunk(1, 1);
    load_chunk(2, 2);

    for (int j = 0; j < NCHUNK; j++) {
        if (j < 8)       { CP_WAIT(2); }
        else if (j == 8) { CP_WAIT(1); }
        else             { CP_WAIT(0); }
        __syncthreads();

        const int stage = j & 3;
        const uint32_t sA = smem_base + stage * STAGE_BYTES;
        const uint32_t sB = sA + A_STAGE_BYTES;

        if (j + 3 < NCHUNK) load_chunk(j + 3, (j + 3) & 3);

#pragma unroll
        for (int ktl = 0; ktl < 2; ktl++) {
            uint32_t a[4][4], b[4][2];
#pragma unroll
            for (int i = 0; i < 4; i++)
                lds128(a[i], sA + (uint32_t)(((ktl * 8) + warp_m * 4 + i) * 32 + lane) * 16);
#pragma unroll
            for (int jn = 0; jn < 4; jn++)
                lds64(b[jn], sB + (uint32_t)(((ktl * 16) + warp_n * 4 + jn) * 32 + lane) * 8);
#pragma unroll
            for (int i = 0; i < 4; i++)
#pragma unroll
                for (int jn = 0; jn < 4; jn++)
                    mma_f16(acc[i][jn], a[i], b[jn]);
        }
    }

    // Epilogue (fp16)
    const size_t rowBase = (size_t)mTile * 128 + warp_m * 64 + (lane >> 2);
    const int colBase = nTile * 128 + warp_n * 32 + 2 * (lane & 3);
#pragma unroll
    for (int i = 0; i < 4; i++) {
        size_t r0 = rowBase + i * 16;
#pragma unroll
        for (int jn = 0; jn < 4; jn++) {
            int col = colBase + jn * 8;
            *(__half2*)&Pout[r0 * CHPAD + col] = __floats2half2_rn(acc[i][jn][0], acc[i][jn][1]);
            *(__half2*)&Pout[(r0 + 8) * CHPAD + col] = __floats2half2_rn(acc[i][jn][2], acc[i][jn][3]);
        }
    }
}

// ---------------------------------------------------------------------------
// Stage 2: warp per m, all 4 coils share the phasor.
// Tr = P0-P1, Ti = P2-P0-P1 ; k[c,m] = (1/300)*sum_h T*exp(-2pi i om0 (h-150))
// Lane loads 4 h per coil per variant (uint2); 4-term fold per coil.
// Block (8 warps = 8 m) reduces loss partials to g_part[blockIdx].
// ---------------------------------------------------------------------------
__global__ void __launch_bounds__(256) stage2_kernel(const float* __restrict__ omega,
                                                     const float* __restrict__ kdata) {
    __shared__ float bred[8];
    const int wid = threadIdx.x >> 5;
    const int lane = threadIdx.x & 31;
    const int m = blockIdx.x * 8 + wid;

    const float om0 = omega[m];
    const size_t rowoff = (size_t)m * CHPAD;
    const uint2* p0 = (const uint2*)(g_P + rowoff);
    const uint2* p1 = (const uint2*)(g_P + PS + rowoff);
    const uint2* p2 = (const uint2*)(g_P + 2 * PS + rowoff);

    float2 e    = phasor(om0 * (float)(4 * lane - 150));  // exp at h0 = 4*lane
    float2 e1   = phasor(om0);
    float2 e2   = cmul(e1, e1);
    float2 e3   = cmul(e2, e1);
    float2 step = phasor(om0 * 128.0f);

    float2 acc[Cn] = {{0,0},{0,0},{0,0},{0,0}};

    for (int idx = lane; idx < 75; idx += 32) {
        uint2 a0[Cn], a1[Cn], a2[Cn];
#pragma unroll
        for (int c = 0; c < Cn; c++) {
            a0[c] = p0[c * 75 + idx];
            a1[c] = p1[c * 75 + idx];
            a2[c] = p2[c * 75 + idx];
        }
#pragma unroll
        for (int c = 0; c < Cn; c++) {
            float2 q0a = __half22float2(*(__half2*)&a0[c].x);
            float2 q0b = __half22float2(*(__half2*)&a0[c].y);
            float2 q1a = __half22float2(*(__half2*)&a1[c].x);
            float2 q1b = __half22float2(*(__half2*)&a1[c].y);
            float2 q2a = __half22float2(*(__half2*)&a2[c].x);
            float2 q2b = __half22float2(*(__half2*)&a2[c].y);

            float tr0 = q0a.x - q1a.x, ti0 = q2a.x - q0a.x - q1a.x;
            float tr1 = q0a.y - q1a.y, ti1 = q2a.y - q0a.y - q1a.y;
            float tr2 = q0b.x - q1b.x, ti2 = q2b.x - q0b.x - q1b.x;
            float tr3 = q0b.y - q1b.y, ti3 = q2b.y - q0b.y - q1b.y;

            float qr = tr0 + tr1 * e1.x - ti1 * e1.y + tr2 * e2.x - ti2 * e2.y
                           + tr3 * e3.x - ti3 * e3.y;
            float qi = ti0 + tr1 * e1.y + ti1 * e1.x + tr2 * e2.y + ti2 * e2.x
                           + tr3 * e3.y + ti3 * e3.x;

            acc[c].x += e.x * qr - e.y * qi;
            acc[c].y += e.x * qi + e.y * qr;
        }
        e = cmul(e, step);
    }

#pragma unroll
    for (int off = 16; off; off >>= 1)
#pragma unroll
        for (int c = 0; c < Cn; c++) {
            acc[c].x += __shfl_down_sync(0xffffffffu, acc[c].x, off);
            acc[c].y += __shfl_down_sync(0xffffffffu, acc[c].y, off);
        }

    if (lane == 0) {
        const float inv = 1.0f / 300.0f;
        float o0 = om0 * TWO_PI_F;
        float o1 = omega[Mn + m] * TWO_PI_F;
        float wgt = sqrtf(o0 * o0 + o1 * o1) + 1.0f;
        float w2 = wgt * wgt;
        float s = 0.0f;
#pragma unroll
        for (int c = 0; c < Cn; c++) {
            float dr = acc[c].x * inv - kdata[2 * (c * Mn + m)];
            float di = acc[c].y * inv - kdata[2 * (c * Mn + m) + 1];
            s += w2 * (dr * dr + di * di);
        }
        bred[wid] = s;
    }
    __syncthreads();
    if (threadIdx.x == 0) {
        float s = 0.0f;
#pragma unroll
        for (int w = 0; w < 8; w++) s += bred[w];
        g_part[blockIdx.x] = s;
    }
}

__global__ void reduce_kernel(float* __restrict__ out) {
    __shared__ float red[256];
    float s = 0.0f;
    for (int i = threadIdx.x; i < 512; i += 256) s += g_part[i];
    red[threadIdx.x] = s;
    __syncthreads();
    for (int off = 128; off; off >>= 1) {
        if (threadIdx.x < off) red[threadIdx.x] += red[threadIdx.x + off];
        __syncthreads();
    }
    if (threadIdx.x == 0) out[0] = red[0] / (float)(2 * Cn * Mn);
}

// ---------------------------------------------------------------------------
extern "C" void kernel_launch(void* const* d_in, const int* in_sizes, int n_in,
                              void* d_out, int out_size) {
    const float* img   = (const float*)d_in[0];   // (300,300,1)
    const float* kdata = (const float*)d_in[1];   // (1,4,4096,2)
    const float* omega = (const float*)d_in[2];   // (1,2,4096)
    const float* csm   = (const float*)d_in[4];   // (4,300,300,2)
    float* out = (float*)d_out;

    prep_Ap<<<(AP_V + 255) / 256, 256>>>(omega);
    prep_Bp<<<(BP_V + 255) / 256, 256>>>(img, csm);

    cudaFuncSetAttribute(gemm_kernel, cudaFuncAttributeMaxDynamicSharedMemorySize, SMEM_DYN);
    gemm_kernel<<<dim3(Mn / 128, CHPAD / 128, 3), 256, SMEM_DYN>>>();

    stage2_kernel<<<512, 256>>>(omega, kdata);
    reduce_kernel<<<1, 256>>>(out);
}